// round 4
// baseline (speedup 1.0000x reference)
#include <cuda_runtime.h>
#include <cuda_fp16.h>
#include <cuda_bf16.h>

#define C 128
#define N_MAX 50000
#define E_MAX 625000
#define NB 148          // persistent prep blocks (<= SM count, all co-resident)
#define TPB 512

// ---------------- scratch (static device globals; no allocation) -------------
__device__ __half g_xwh[N_MAX * C];      // X @ W, fp16
__device__ float g_dinv[N_MAX];          // deg^{-1/2}
__device__ int   g_deg[N_MAX];           // out-degree by row
__device__ int   g_cnt[N_MAX];           // in-degree by col (CSR counts)
__device__ int   g_offL[N_MAX];          // tile-local exclusive offsets
__device__ int   g_off[N_MAX + 1];       // final CSR offsets (for k_agg)
__device__ int   g_cur[N_MAX];           // scatter cursors (zeroed each launch)
__device__ int   g_bsum[128];            // scan tile sums
__device__ int2  g_edge[E_MAX];          // packed: {src | key<<16, norm_bits}
__device__ float g_combo[60 * C];        // emb0[f0]+emb1[f1]+emb2[f2]
__device__ int   g_tick;                 // monotonic launch ticket
__device__ int   g_bar;                  // monotonic barrier counter

// grid barrier: monotonic target, no reset needed across graph replays
__device__ __forceinline__ void gbar(int target) {
    __syncthreads();
    if (threadIdx.x == 0) {
        __threadfence();
        atomicAdd(&g_bar, 1);
        while (*((volatile int*)&g_bar) < target) __nanosleep(40);
    }
    __syncthreads();
}

// ------------- fused preprocessing: zero+combo / count / scan / scatter ------
__global__ void __launch_bounds__(TPB, 1)
k_prep(const int* __restrict__ row, const int* __restrict__ col,
       const int* __restrict__ ef,
       const float* __restrict__ e0, const float* __restrict__ e1,
       const float* __restrict__ e2, int n, int e) {
    __shared__ int s_base;
    __shared__ int s_scan[128];
    __shared__ int wsum[16];

    int tid = threadIdx.x;
    if (tid == 0) {
        int t = atomicAdd(&g_tick, 1);
        s_base = (t / NB) * (3 * NB);    // 3 barriers per launch
    }
    __syncthreads();
    int base = s_base;
    int gtid = blockIdx.x * TPB + tid;
    int nth  = NB * TPB;
    int nbT  = (n + TPB - 1) / TPB;      // scan tiles (98)

    // P0: zero counters/cursors + combo table
    for (int i = gtid; i < n; i += nth) { g_deg[i] = 0; g_cnt[i] = 0; g_cur[i] = 0; }
    for (int i = gtid; i < 60 * C; i += nth) {
        int c = i >> 7, k = i & 127;
        g_combo[i] = e0[(c % 5) * C + k] + e1[((c / 5) % 6) * C + k]
                   + e2[(c / 30) * C + k];
    }
    gbar(base + NB);

    // P1: degree histograms
    for (int i = gtid; i < e; i += nth) {
        atomicAdd(&g_deg[row[i]], 1);
        atomicAdd(&g_cnt[col[i]], 1);
    }
    gbar(base + 2 * NB);

    // P2: tile-local exclusive scan of g_cnt (blocks 0..nbT-1) + dinv
    if (blockIdx.x < nbT) {
        int lane = tid & 31, wid = tid >> 5;
        int i = blockIdx.x * TPB + tid;
        int v = (i < n) ? g_cnt[i] : 0;
        int x = v;
        #pragma unroll
        for (int o = 1; o < 32; o <<= 1) {
            int t = __shfl_up_sync(0xFFFFFFFFu, x, o);
            if (lane >= o) x += t;
        }
        if (lane == 31) wsum[wid] = x;
        __syncthreads();
        if (wid == 0 && lane < 16) {
            int s = wsum[lane];
            #pragma unroll
            for (int o = 1; o < 16; o <<= 1) {
                int t = __shfl_up_sync(0xFFFFu, s, o);
                if (lane >= o) s += t;
            }
            wsum[lane] = s;
        }
        __syncthreads();
        int incl = x + (wid > 0 ? wsum[wid - 1] : 0);
        if (i < n) {
            g_offL[i] = incl - v;
            int d = g_deg[i];
            g_dinv[i] = (d > 0) ? rsqrtf((float)d) : 0.0f;
        }
        if (tid == TPB - 1) g_bsum[blockIdx.x] = incl;
    }
    gbar(base + 3 * NB);

    // P3a: every block redundantly scans the 98 tile sums (inclusive)
    if (tid < 128) s_scan[tid] = (tid < nbT) ? g_bsum[tid] : 0;
    __syncthreads();
    #pragma unroll
    for (int o = 1; o < 128; o <<= 1) {
        int t = (tid < 128 && tid >= o) ? s_scan[tid - o] : 0;
        __syncthreads();
        if (tid < 128) s_scan[tid] += t;
        __syncthreads();
    }
    // exclusive tile prefix = s_scan[tile-1]

    // P3b: finalize g_off for k_agg (independent of scatter below)
    for (int i = gtid; i < n; i += nth) {
        int t = i >> 9;
        g_off[i] = g_offL[i] + (t > 0 ? s_scan[t - 1] : 0);
    }
    if (gtid == 0) g_off[n] = e;

    // P3c: scatter edges (uses tile-local offsets + smem prefixes + cursor)
    for (int i = gtid; i < e; i += nth) {
        int r = row[i], c = col[i];
        int t = c >> 9;
        int p = g_offL[c] + (t > 0 ? s_scan[t - 1] : 0) + atomicAdd(&g_cur[c], 1);
        int key = ef[3 * i] + 5 * ef[3 * i + 1] + 30 * ef[3 * i + 2];
        float nrm = g_dinv[r] * g_dinv[c];
        g_edge[p] = make_int2(r | (key << 16), __float_as_int(nrm));
    }
}

// ---------------- tf32 tensor-core GEMM (fp16 output) ------------------------
__device__ __forceinline__ unsigned f2tf(float f) {
    unsigned r;
    asm("cvt.rna.tf32.f32 %0, %1;" : "=r"(r) : "f"(f));
    return r;
}

#define GP 132  // smem pitch (floats)

__global__ void k_gemm(const float* __restrict__ x, const float* __restrict__ w, int n) {
    extern __shared__ unsigned smem[];
    unsigned* As = smem;             // 64  x GP
    unsigned* Bs = smem + 64 * GP;   // 128 x GP   (B stored [n][k])
    int tid = threadIdx.x;
    int row0 = blockIdx.x * 64;

    #pragma unroll
    for (int it = 0; it < 8; it++) {
        int flat = tid + 256 * it;        // 2048 float4s
        int k4 = flat & 31, m = flat >> 5;
        int gr = row0 + m;
        float4 v = make_float4(0.f, 0.f, 0.f, 0.f);
        if (gr < n) v = ((const float4*)x)[gr * 32 + k4];
        unsigned* p = &As[m * GP + 4 * k4];
        p[0] = f2tf(v.x); p[1] = f2tf(v.y); p[2] = f2tf(v.z); p[3] = f2tf(v.w);
    }
    #pragma unroll
    for (int it = 0; it < 16; it++) {
        int flat = tid + 256 * it;        // 4096 quads
        int nn = flat & 127, k0 = 4 * (flat >> 7);
        unsigned q0 = f2tf(w[(k0 + 0) * C + nn]);
        unsigned q1 = f2tf(w[(k0 + 1) * C + nn]);
        unsigned q2 = f2tf(w[(k0 + 2) * C + nn]);
        unsigned q3 = f2tf(w[(k0 + 3) * C + nn]);
        unsigned* p = &Bs[nn * GP + k0];
        p[0] = q0; p[1] = q1; p[2] = q2; p[3] = q3;
    }
    __syncthreads();

    int wid = tid >> 5, lane = tid & 31;
    int g = lane >> 2, t4 = lane & 3;
    int wm = (wid & 1) * 32;     // warp m base
    int wn = (wid >> 1) * 32;    // warp n base

    float c[2][4][4];
    #pragma unroll
    for (int a = 0; a < 2; a++)
        #pragma unroll
        for (int b = 0; b < 4; b++)
            #pragma unroll
            for (int k = 0; k < 4; k++) c[a][b][k] = 0.f;

    #pragma unroll
    for (int s = 0; s < 16; s++) {
        int k0 = s * 8;
        unsigned a0[2], a1[2], a2[2], a3[2];
        #pragma unroll
        for (int mt = 0; mt < 2; mt++) {
            const unsigned* ap = &As[(wm + mt * 16 + g) * GP + k0 + t4];
            a0[mt] = ap[0];
            a1[mt] = ap[8 * GP];
            a2[mt] = ap[4];
            a3[mt] = ap[8 * GP + 4];
        }
        unsigned b0[4], b1[4];
        #pragma unroll
        for (int nt = 0; nt < 4; nt++) {
            const unsigned* bp = &Bs[(wn + nt * 8 + g) * GP + k0 + t4];
            b0[nt] = bp[0];
            b1[nt] = bp[4];
        }
        #pragma unroll
        for (int mt = 0; mt < 2; mt++)
            #pragma unroll
            for (int nt = 0; nt < 4; nt++) {
                asm volatile(
                    "mma.sync.aligned.m16n8k8.row.col.f32.tf32.tf32.f32 "
                    "{%0,%1,%2,%3},{%4,%5,%6,%7},{%8,%9},{%0,%1,%2,%3};\n"
                    : "+f"(c[mt][nt][0]), "+f"(c[mt][nt][1]),
                      "+f"(c[mt][nt][2]), "+f"(c[mt][nt][3])
                    : "r"(a0[mt]), "r"(a1[mt]), "r"(a2[mt]), "r"(a3[mt]),
                      "r"(b0[nt]), "r"(b1[nt]));
            }
    }

    #pragma unroll
    for (int mt = 0; mt < 2; mt++) {
        int r_lo = row0 + wm + mt * 16 + g;
        int r_hi = r_lo + 8;
        #pragma unroll
        for (int nt = 0; nt < 4; nt++) {
            int colp = wn + nt * 8 + 2 * t4;
            if (r_lo < n)
                *(__half2*)&g_xwh[r_lo * C + colp] = __floats2half2_rn(c[mt][nt][0], c[mt][nt][1]);
            if (r_hi < n)
                *(__half2*)&g_xwh[r_hi * C + colp] = __floats2half2_rn(c[mt][nt][2], c[mt][nt][3]);
        }
    }
}

// ---------------- aggregation: one warp per destination node ------------------
__device__ __forceinline__ void agg_edge(int2 m, int lane, float4& acc) {
    int src = m.x & 0xFFFF;
    int key = m.x >> 16;
    float nrm = __int_as_float(m.y);
    uint2 h = ((const uint2*)g_xwh)[src * 32 + lane];        // 4 fp16 channels
    float2 lo = __half22float2(*(__half2*)&h.x);
    float2 hi = __half22float2(*(__half2*)&h.y);
    float4 cv = ((const float4*)g_combo)[key * 32 + lane];
    acc.x += nrm * (lo.x + cv.x);
    acc.y += nrm * (lo.y + cv.y);
    acc.z += nrm * (hi.x + cv.z);
    acc.w += nrm * (hi.y + cv.w);
}

__global__ void k_agg(float* __restrict__ out, int n) {
    int warp = (blockIdx.x * blockDim.x + threadIdx.x) >> 5;
    int lane = threadIdx.x & 31;
    if (warp >= n) return;
    int beg = g_off[warp], end = g_off[warp + 1];
    float4 acc = make_float4(0.f, 0.f, 0.f, 0.f);
    int j = beg;
    for (; j + 3 < end; j += 4) {
        int2 m0 = g_edge[j];
        int2 m1 = g_edge[j + 1];
        int2 m2 = g_edge[j + 2];
        int2 m3 = g_edge[j + 3];
        agg_edge(m0, lane, acc);
        agg_edge(m1, lane, acc);
        agg_edge(m2, lane, acc);
        agg_edge(m3, lane, acc);
    }
    for (; j < end; j++) {
        agg_edge(g_edge[j], lane, acc);
    }
    ((float4*)out)[warp * 32 + lane] = acc;
}

// ---------------- launch ------------------------------------------------------

extern "C" void kernel_launch(void* const* d_in, const int* in_sizes, int n_in,
                              void* d_out, int out_size) {
    const float* x      = (const float*)d_in[0];
    const int*   eidx   = (const int*)d_in[1];
    const int*   efeat  = (const int*)d_in[2];
    const float* weight = (const float*)d_in[3];
    const float* emb0   = (const float*)d_in[4];
    const float* emb1   = (const float*)d_in[5];
    const float* emb2   = (const float*)d_in[6];
    float*       out    = (float*)d_out;

    int n = in_sizes[0] / C;       // 50000
    int e = in_sizes[1] / 2;       // 625000
    const int* row = eidx;
    const int* col = eidx + e;

    static cudaStream_t s2 = nullptr;
    static cudaEvent_t evFork = nullptr, evJoin = nullptr;
    if (!s2) {
        cudaStreamCreateWithFlags(&s2, cudaStreamNonBlocking);
        cudaEventCreateWithFlags(&evFork, cudaEventDisableTiming);
        cudaEventCreateWithFlags(&evJoin, cudaEventDisableTiming);
    }

    int gemm_smem = (64 + 128) * GP * (int)sizeof(unsigned);  // 101376
    cudaFuncSetAttribute(k_gemm, cudaFuncAttributeMaxDynamicSharedMemorySize, gemm_smem);

    // fork: gemm runs on s2 in parallel with prep on the main stream
    cudaEventRecord(evFork, 0);
    cudaStreamWaitEvent(s2, evFork, 0);

    k_gemm<<<(n + 63) / 64, 256, gemm_smem, s2>>>(x, weight, n);
    k_prep<<<NB, TPB>>>(row, col, efeat, emb0, emb1, emb2, n, e);

    // join, then aggregate
    cudaEventRecord(evJoin, s2);
    cudaStreamWaitEvent(0, evJoin, 0);

    k_agg<<<(n * 32 + 255) / 256, 256>>>(out, n);
}

// round 6
// speedup vs baseline: 1.8361x; 1.8361x over previous
#include <cuda_runtime.h>
#include <cuda_fp16.h>
#include <cuda_bf16.h>

#define C 128
#define N_MAX 50000
#define E_MAX 625000

// ---------------- scratch (static device globals; no allocation) -------------
__device__ __half g_xwh[N_MAX * C];      // X @ W, fp16
__device__ float g_dinv[N_MAX];          // deg^{-1/2}
__device__ int   g_deg[N_MAX];           // out-degree by row
__device__ int   g_cnt[N_MAX];           // in-degree by col (CSR counts)
__device__ int   g_off[N_MAX + 1];       // CSR offsets
__device__ int   g_cur[N_MAX];           // scatter cursors
__device__ int   g_bsum[128];            // scan block sums
__device__ int2  g_edge[E_MAX];          // packed: {src | key<<16, norm_bits}
__device__ float g_combo[60 * C];        // emb0[f0]+emb1[f1]+emb2[f2]

// ---------------- fused init: zero counters + combo table --------------------
__global__ void k_init(int n, const float* __restrict__ e0,
                       const float* __restrict__ e1, const float* __restrict__ e2) {
    int i = blockIdx.x * blockDim.x + threadIdx.x;
    if (i < n) { g_deg[i] = 0; g_cnt[i] = 0; }
    if (i < 60 * C) {
        int c = i >> 7, k = i & 127;
        int f0 = c % 5, f1 = (c / 5) % 6, f2 = c / 30;
        g_combo[i] = e0[f0 * C + k] + e1[f1 * C + k] + e2[f2 * C + k];
    }
}

__global__ void k_count(const int* __restrict__ row, const int* __restrict__ col, int e) {
    int i = blockIdx.x * blockDim.x + threadIdx.x;
    if (i < e) {
        atomicAdd(&g_deg[row[i]], 1);
        atomicAdd(&g_cnt[col[i]], 1);
    }
}

// -------- scan stage 1: tile-local exclusive scan + block sums + fused dinv --
__global__ void k_scan1(int n) {   // 512 threads / block, 1 elem / thread
    __shared__ int wsum[16];
    int tid = threadIdx.x, lane = tid & 31, wid = tid >> 5;
    int i = blockIdx.x * 512 + tid;
    int v = (i < n) ? g_cnt[i] : 0;
    int x = v;
    #pragma unroll
    for (int o = 1; o < 32; o <<= 1) {
        int t = __shfl_up_sync(0xFFFFFFFFu, x, o);
        if (lane >= o) x += t;
    }
    if (lane == 31) wsum[wid] = x;
    __syncthreads();
    if (wid == 0 && lane < 16) {
        int s = wsum[lane];
        #pragma unroll
        for (int o = 1; o < 16; o <<= 1) {
            int t = __shfl_up_sync(0xFFFFu, s, o);
            if (lane >= o) s += t;
        }
        wsum[lane] = s;
    }
    __syncthreads();
    int incl = x + (wid > 0 ? wsum[wid - 1] : 0);
    if (i < n) {
        g_off[i] = incl - v;          // tile-local exclusive
        int d = g_deg[i];
        g_dinv[i] = (d > 0) ? rsqrtf((float)d) : 0.0f;
    }
    if (tid == 511) g_bsum[blockIdx.x] = incl;
}

// -------- scan stage 2+3 fused: every block redundantly scans block sums -----
__global__ void k_scan23(int n, int nb, int e) {
    __shared__ int s[128];
    int tid = threadIdx.x;
    if (tid < 128) s[tid] = (tid < nb) ? g_bsum[tid] : 0;
    __syncthreads();
    #pragma unroll
    for (int o = 1; o < 128; o <<= 1) {
        int t = (tid < 128 && tid >= o) ? s[tid - o] : 0;
        __syncthreads();
        if (tid < 128) s[tid] += t;
        __syncthreads();
    }
    int off = (blockIdx.x > 0) ? s[blockIdx.x - 1] : 0;
    int i = blockIdx.x * 512 + tid;
    if (i < n) {
        int val = g_off[i] + off;
        g_off[i] = val;
        g_cur[i] = val;
    }
    if (i == 0) g_off[n] = e;
}

// bucket edges by destination; packed 8-byte record per edge
__global__ void k_scatter(const int* __restrict__ row, const int* __restrict__ col,
                          const int* __restrict__ ef, int e) {
    int i = blockIdx.x * blockDim.x + threadIdx.x;
    if (i < e) {
        int r = row[i], c = col[i];
        int p = atomicAdd(&g_cur[c], 1);
        int key = ef[3 * i] + 5 * ef[3 * i + 1] + 30 * ef[3 * i + 2];
        float nrm = g_dinv[r] * g_dinv[c];
        g_edge[p] = make_int2(r | (key << 16), __float_as_int(nrm));
    }
}

// ---------------- tf32 tensor-core GEMM (fp16 output) ------------------------
__device__ __forceinline__ unsigned f2tf(float f) {
    unsigned r;
    asm("cvt.rna.tf32.f32 %0, %1;" : "=r"(r) : "f"(f));
    return r;
}

#define GP 132  // smem pitch (floats)

__global__ void k_gemm(const float* __restrict__ x, const float* __restrict__ w, int n) {
    extern __shared__ unsigned smem[];
    unsigned* As = smem;             // 64  x GP
    unsigned* Bs = smem + 64 * GP;   // 128 x GP   (B stored [n][k])
    int tid = threadIdx.x;
    int row0 = blockIdx.x * 64;

    #pragma unroll
    for (int it = 0; it < 8; it++) {
        int flat = tid + 256 * it;        // 2048 float4s
        int k4 = flat & 31, m = flat >> 5;
        int gr = row0 + m;
        float4 v = make_float4(0.f, 0.f, 0.f, 0.f);
        if (gr < n) v = ((const float4*)x)[gr * 32 + k4];
        unsigned* p = &As[m * GP + 4 * k4];
        p[0] = f2tf(v.x); p[1] = f2tf(v.y); p[2] = f2tf(v.z); p[3] = f2tf(v.w);
    }
    #pragma unroll
    for (int it = 0; it < 16; it++) {
        int flat = tid + 256 * it;        // 4096 quads
        int nn = flat & 127, k0 = 4 * (flat >> 7);
        unsigned q0 = f2tf(w[(k0 + 0) * C + nn]);
        unsigned q1 = f2tf(w[(k0 + 1) * C + nn]);
        unsigned q2 = f2tf(w[(k0 + 2) * C + nn]);
        unsigned q3 = f2tf(w[(k0 + 3) * C + nn]);
        unsigned* p = &Bs[nn * GP + k0];
        p[0] = q0; p[1] = q1; p[2] = q2; p[3] = q3;
    }
    __syncthreads();

    int wid = tid >> 5, lane = tid & 31;
    int g = lane >> 2, t4 = lane & 3;
    int wm = (wid & 1) * 32;     // warp m base
    int wn = (wid >> 1) * 32;    // warp n base

    float c[2][4][4];
    #pragma unroll
    for (int a = 0; a < 2; a++)
        #pragma unroll
        for (int b = 0; b < 4; b++)
            #pragma unroll
            for (int k = 0; k < 4; k++) c[a][b][k] = 0.f;

    #pragma unroll
    for (int s = 0; s < 16; s++) {
        int k0 = s * 8;
        unsigned a0[2], a1[2], a2[2], a3[2];
        #pragma unroll
        for (int mt = 0; mt < 2; mt++) {
            const unsigned* ap = &As[(wm + mt * 16 + g) * GP + k0 + t4];
            a0[mt] = ap[0];
            a1[mt] = ap[8 * GP];
            a2[mt] = ap[4];
            a3[mt] = ap[8 * GP + 4];
        }
        unsigned b0[4], b1[4];
        #pragma unroll
        for (int nt = 0; nt < 4; nt++) {
            const unsigned* bp = &Bs[(wn + nt * 8 + g) * GP + k0 + t4];
            b0[nt] = bp[0];
            b1[nt] = bp[4];
        }
        #pragma unroll
        for (int mt = 0; mt < 2; mt++)
            #pragma unroll
            for (int nt = 0; nt < 4; nt++) {
                asm volatile(
                    "mma.sync.aligned.m16n8k8.row.col.f32.tf32.tf32.f32 "
                    "{%0,%1,%2,%3},{%4,%5,%6,%7},{%8,%9},{%0,%1,%2,%3};\n"
                    : "+f"(c[mt][nt][0]), "+f"(c[mt][nt][1]),
                      "+f"(c[mt][nt][2]), "+f"(c[mt][nt][3])
                    : "r"(a0[mt]), "r"(a1[mt]), "r"(a2[mt]), "r"(a3[mt]),
                      "r"(b0[nt]), "r"(b1[nt]));
            }
    }

    #pragma unroll
    for (int mt = 0; mt < 2; mt++) {
        int r_lo = row0 + wm + mt * 16 + g;
        int r_hi = r_lo + 8;
        #pragma unroll
        for (int nt = 0; nt < 4; nt++) {
            int colp = wn + nt * 8 + 2 * t4;
            if (r_lo < n)
                *(__half2*)&g_xwh[r_lo * C + colp] = __floats2half2_rn(c[mt][nt][0], c[mt][nt][1]);
            if (r_hi < n)
                *(__half2*)&g_xwh[r_hi * C + colp] = __floats2half2_rn(c[mt][nt][2], c[mt][nt][3]);
        }
    }
}

// ---------------- aggregation: one warp per destination node ------------------
__device__ __forceinline__ void agg_edge(int2 m, int lane, float4& acc) {
    int src = m.x & 0xFFFF;
    int key = m.x >> 16;
    float nrm = __int_as_float(m.y);
    uint2 h = __ldg(&((const uint2*)g_xwh)[src * 32 + lane]); // 4 fp16 channels
    float2 lo = __half22float2(*(__half2*)&h.x);
    float2 hi = __half22float2(*(__half2*)&h.y);
    float4 cv = __ldg(&((const float4*)g_combo)[key * 32 + lane]);
    acc.x += nrm * (lo.x + cv.x);
    acc.y += nrm * (lo.y + cv.y);
    acc.z += nrm * (hi.x + cv.z);
    acc.w += nrm * (hi.y + cv.w);
}

__global__ void k_agg(float* __restrict__ out, int n) {
    int warp = (blockIdx.x * blockDim.x + threadIdx.x) >> 5;
    int lane = threadIdx.x & 31;
    if (warp >= n) return;
    int beg = g_off[warp], end = g_off[warp + 1];
    float4 acc = make_float4(0.f, 0.f, 0.f, 0.f);
    int j = beg;
    for (; j + 3 < end; j += 4) {
        int2 m0 = g_edge[j];
        int2 m1 = g_edge[j + 1];
        int2 m2 = g_edge[j + 2];
        int2 m3 = g_edge[j + 3];
        agg_edge(m0, lane, acc);
        agg_edge(m1, lane, acc);
        agg_edge(m2, lane, acc);
        agg_edge(m3, lane, acc);
    }
    for (; j < end; j++) {
        agg_edge(g_edge[j], lane, acc);
    }
    ((float4*)out)[warp * 32 + lane] = acc;
}

// ---------------- launch ------------------------------------------------------

extern "C" void kernel_launch(void* const* d_in, const int* in_sizes, int n_in,
                              void* d_out, int out_size) {
    const float* x      = (const float*)d_in[0];
    const int*   eidx   = (const int*)d_in[1];
    const int*   efeat  = (const int*)d_in[2];
    const float* weight = (const float*)d_in[3];
    const float* emb0   = (const float*)d_in[4];
    const float* emb1   = (const float*)d_in[5];
    const float* emb2   = (const float*)d_in[6];
    float*       out    = (float*)d_out;

    int n = in_sizes[0] / C;       // 50000
    int e = in_sizes[1] / 2;       // 625000
    const int* row = eidx;
    const int* col = eidx + e;

    static cudaStream_t s2 = nullptr;
    static cudaEvent_t evFork = nullptr, evJoin = nullptr;
    if (!s2) {
        cudaStreamCreateWithFlags(&s2, cudaStreamNonBlocking);
        cudaEventCreateWithFlags(&evFork, cudaEventDisableTiming);
        cudaEventCreateWithFlags(&evJoin, cudaEventDisableTiming);
    }

    int gemm_smem = (64 + 128) * GP * (int)sizeof(unsigned);  // 101376
    cudaFuncSetAttribute(k_gemm, cudaFuncAttributeMaxDynamicSharedMemorySize, gemm_smem);

    int tpb = 256;
    int nb = (n + 511) / 512;      // scan tiles (98 <= 128)

    // fork: gemm on s2 runs concurrently with the prep chain on stream 0
    cudaEventRecord(evFork, 0);
    cudaStreamWaitEvent(s2, evFork, 0);
    k_gemm   <<<(n + 63) / 64, 256, gemm_smem, s2>>>(x, weight, n);

    k_init   <<<(n + tpb - 1) / tpb, tpb>>>(n, emb0, emb1, emb2);
    k_count  <<<(e + tpb - 1) / tpb, tpb>>>(row, col, e);
    k_scan1  <<<nb, 512>>>(n);
    k_scan23 <<<nb, 512>>>(n, nb, e);
    k_scatter<<<(e + tpb - 1) / tpb, tpb>>>(row, col, efeat, e);

    // join, then aggregate
    cudaEventRecord(evJoin, s2);
    cudaStreamWaitEvent(0, evJoin, 0);
    k_agg    <<<(n * 32 + tpb - 1) / tpb, tpb>>>(out, n);
}

// round 13
// speedup vs baseline: 1.8392x; 1.0017x over previous
#include <cuda_runtime.h>
#include <cuda_fp16.h>
#include <cuda_bf16.h>

#define C 128
#define N_MAX 50000
#define E_MAX 625000

// ---------------- scratch (static device globals; no allocation) -------------
// Invariant: g_deg, g_cnt, g_cur are ZERO at entry to every kernel_launch
// execution (zero at module load; restored by scan1/agg within each run).
__device__ __half g_xwh[N_MAX * C];      // X @ W, fp16
__device__ float g_dinv[N_MAX];          // deg^{-1/2}
__device__ int   g_deg[N_MAX];           // out-degree by row   (restored to 0)
__device__ int   g_cnt[N_MAX];           // in-degree by col    (restored to 0)
__device__ int   g_offL[N_MAX];          // tile-local exclusive offsets
__device__ int   g_off[N_MAX + 1];       // final CSR offsets (for k_agg)
__device__ int   g_cur[N_MAX];           // scatter cursors     (restored to 0)
__device__ int   g_bsum[128];            // scan tile sums
__device__ int2  g_edge[E_MAX];          // packed: {src | key<<16, norm_bits}
__device__ float g_combo[60 * C];        // emb0[f0]+emb1[f1]+emb2[f2]

// ---------------- count: degree histograms + combo table ---------------------
__global__ void k_count(const int* __restrict__ row, const int* __restrict__ col,
                        const float* __restrict__ e0, const float* __restrict__ e1,
                        const float* __restrict__ e2, int e) {
    int i = blockIdx.x * blockDim.x + threadIdx.x;
    if (i < e) {
        atomicAdd(&g_deg[row[i]], 1);
        atomicAdd(&g_cnt[col[i]], 1);
    }
    if (i < 60 * C) {
        int c = i >> 7, k = i & 127;
        g_combo[i] = e0[(c % 5) * C + k] + e1[((c / 5) % 6) * C + k]
                   + e2[(c / 30) * C + k];
    }
}

// -------- scan1: tile-local exclusive scan + tile sums + dinv; restore zeros -
__global__ void k_scan1(int n) {   // 512 threads / block
    __shared__ int wsum[16];
    int tid = threadIdx.x, lane = tid & 31, wid = tid >> 5;
    int i = blockIdx.x * 512 + tid;
    int v = 0;
    if (i < n) {
        v = g_cnt[i];
        g_cnt[i] = 0;                         // restore invariant
        int d = g_deg[i];
        g_deg[i] = 0;                         // restore invariant
        g_dinv[i] = (d > 0) ? rsqrtf((float)d) : 0.0f;
    }
    int x = v;
    #pragma unroll
    for (int o = 1; o < 32; o <<= 1) {
        int t = __shfl_up_sync(0xFFFFFFFFu, x, o);
        if (lane >= o) x += t;
    }
    if (lane == 31) wsum[wid] = x;
    __syncthreads();
    if (wid == 0 && lane < 16) {
        int s = wsum[lane];
        #pragma unroll
        for (int o = 1; o < 16; o <<= 1) {
            int t = __shfl_up_sync(0xFFFFu, s, o);
            if (lane >= o) s += t;
        }
        wsum[lane] = s;
    }
    __syncthreads();
    int incl = x + (wid > 0 ? wsum[wid - 1] : 0);
    if (i < n) g_offL[i] = incl - v;          // tile-local exclusive
    if (tid == 511) g_bsum[blockIdx.x] = incl;
}

// -------- fused: redundant smem scan of tile sums + finalize g_off + scatter -
__global__ void k_sprep(const int* __restrict__ row, const int* __restrict__ col,
                        const int* __restrict__ ef, int n, int nbT, int e) {
    __shared__ int pre[128];
    int tid = threadIdx.x;
    if (tid < 128) pre[tid] = (tid < nbT) ? g_bsum[tid] : 0;
    __syncthreads();
    #pragma unroll
    for (int o = 1; o < 128; o <<= 1) {
        int t = (tid < 128 && tid >= o) ? pre[tid - o] : 0;
        __syncthreads();
        if (tid < 128) pre[tid] += t;
        __syncthreads();
    }
    int gtid = blockIdx.x * blockDim.x + tid;

    // finalize g_off for k_agg (one pass; gridDim covers e >= n)
    if (gtid < n) {
        int t = gtid >> 9;
        g_off[gtid] = g_offL[gtid] + (t > 0 ? pre[t - 1] : 0);
    }
    if (gtid == 0) g_off[n] = e;

    // scatter edges
    if (gtid < e) {
        int r = row[gtid], c = col[gtid];
        int t = c >> 9;
        int p = g_offL[c] + (t > 0 ? pre[t - 1] : 0) + atomicAdd(&g_cur[c], 1);
        int key = ef[3 * gtid] + 5 * ef[3 * gtid + 1] + 30 * ef[3 * gtid + 2];
        float nrm = g_dinv[r] * g_dinv[c];
        g_edge[p] = make_int2(r | (key << 16), __float_as_int(nrm));
    }
}

// ---------------- tf32 tensor-core GEMM (fp16 output) ------------------------
__device__ __forceinline__ unsigned f2tf(float f) {
    unsigned r;
    asm("cvt.rna.tf32.f32 %0, %1;" : "=r"(r) : "f"(f));
    return r;
}

#define GP 132  // smem pitch (floats)

__global__ void k_gemm(const float* __restrict__ x, const float* __restrict__ w, int n) {
    extern __shared__ unsigned smem[];
    unsigned* As = smem;             // 64  x GP
    unsigned* Bs = smem + 64 * GP;   // 128 x GP   (B stored [n][k])
    int tid = threadIdx.x;
    int row0 = blockIdx.x * 64;

    #pragma unroll
    for (int it = 0; it < 8; it++) {
        int flat = tid + 256 * it;        // 2048 float4s
        int k4 = flat & 31, m = flat >> 5;
        int gr = row0 + m;
        float4 v = make_float4(0.f, 0.f, 0.f, 0.f);
        if (gr < n) v = ((const float4*)x)[gr * 32 + k4];
        unsigned* p = &As[m * GP + 4 * k4];
        p[0] = f2tf(v.x); p[1] = f2tf(v.y); p[2] = f2tf(v.z); p[3] = f2tf(v.w);
    }
    #pragma unroll
    for (int it = 0; it < 16; it++) {
        int flat = tid + 256 * it;        // 4096 quads
        int nn = flat & 127, k0 = 4 * (flat >> 7);
        unsigned q0 = f2tf(w[(k0 + 0) * C + nn]);
        unsigned q1 = f2tf(w[(k0 + 1) * C + nn]);
        unsigned q2 = f2tf(w[(k0 + 2) * C + nn]);
        unsigned q3 = f2tf(w[(k0 + 3) * C + nn]);
        unsigned* p = &Bs[nn * GP + k0];
        p[0] = q0; p[1] = q1; p[2] = q2; p[3] = q3;
    }
    __syncthreads();

    int wid = tid >> 5, lane = tid & 31;
    int g = lane >> 2, t4 = lane & 3;
    int wm = (wid & 1) * 32;     // warp m base
    int wn = (wid >> 1) * 32;    // warp n base

    float c[2][4][4];
    #pragma unroll
    for (int a = 0; a < 2; a++)
        #pragma unroll
        for (int b = 0; b < 4; b++)
            #pragma unroll
            for (int k = 0; k < 4; k++) c[a][b][k] = 0.f;

    #pragma unroll
    for (int s = 0; s < 16; s++) {
        int k0 = s * 8;
        unsigned a0[2], a1[2], a2[2], a3[2];
        #pragma unroll
        for (int mt = 0; mt < 2; mt++) {
            const unsigned* ap = &As[(wm + mt * 16 + g) * GP + k0 + t4];
            a0[mt] = ap[0];
            a1[mt] = ap[8 * GP];
            a2[mt] = ap[4];
            a3[mt] = ap[8 * GP + 4];
        }
        unsigned b0[4], b1[4];
        #pragma unroll
        for (int nt = 0; nt < 4; nt++) {
            const unsigned* bp = &Bs[(wn + nt * 8 + g) * GP + k0 + t4];
            b0[nt] = bp[0];
            b1[nt] = bp[4];
        }
        #pragma unroll
        for (int mt = 0; mt < 2; mt++)
            #pragma unroll
            for (int nt = 0; nt < 4; nt++) {
                asm volatile(
                    "mma.sync.aligned.m16n8k8.row.col.f32.tf32.tf32.f32 "
                    "{%0,%1,%2,%3},{%4,%5,%6,%7},{%8,%9},{%0,%1,%2,%3};\n"
                    : "+f"(c[mt][nt][0]), "+f"(c[mt][nt][1]),
                      "+f"(c[mt][nt][2]), "+f"(c[mt][nt][3])
                    : "r"(a0[mt]), "r"(a1[mt]), "r"(a2[mt]), "r"(a3[mt]),
                      "r"(b0[nt]), "r"(b1[nt]));
            }
    }

    #pragma unroll
    for (int mt = 0; mt < 2; mt++) {
        int r_lo = row0 + wm + mt * 16 + g;
        int r_hi = r_lo + 8;
        #pragma unroll
        for (int nt = 0; nt < 4; nt++) {
            int colp = wn + nt * 8 + 2 * t4;
            if (r_lo < n)
                *(__half2*)&g_xwh[r_lo * C + colp] = __floats2half2_rn(c[mt][nt][0], c[mt][nt][1]);
            if (r_hi < n)
                *(__half2*)&g_xwh[r_hi * C + colp] = __floats2half2_rn(c[mt][nt][2], c[mt][nt][3]);
        }
    }
}

// ---------------- aggregation: one warp per destination node ------------------
__device__ __forceinline__ void agg_edge(int2 m, int lane, float4& acc) {
    int src = m.x & 0xFFFF;
    int key = m.x >> 16;
    float nrm = __int_as_float(m.y);
    uint2 h = __ldg(&((const uint2*)g_xwh)[src * 32 + lane]); // 4 fp16 channels
    float2 lo = __half22float2(*(__half2*)&h.x);
    float2 hi = __half22float2(*(__half2*)&h.y);
    float4 cv = __ldg(&((const float4*)g_combo)[key * 32 + lane]);
    acc.x += nrm * (lo.x + cv.x);
    acc.y += nrm * (lo.y + cv.y);
    acc.z += nrm * (hi.x + cv.z);
    acc.w += nrm * (hi.y + cv.w);
}

__global__ void k_agg(float* __restrict__ out, int n) {
    int warp = (blockIdx.x * blockDim.x + threadIdx.x) >> 5;
    int lane = threadIdx.x & 31;
    if (warp >= n) return;
    int beg = g_off[warp], end = g_off[warp + 1];
    if (lane == 0) g_cur[warp] = 0;           // restore invariant
    float4 acc = make_float4(0.f, 0.f, 0.f, 0.f);
    int j = beg;
    for (; j + 3 < end; j += 4) {
        int2 m0 = g_edge[j];
        int2 m1 = g_edge[j + 1];
        int2 m2 = g_edge[j + 2];
        int2 m3 = g_edge[j + 3];
        agg_edge(m0, lane, acc);
        agg_edge(m1, lane, acc);
        agg_edge(m2, lane, acc);
        agg_edge(m3, lane, acc);
    }
    for (; j < end; j++) {
        agg_edge(g_edge[j], lane, acc);
    }
    ((float4*)out)[warp * 32 + lane] = acc;
}

// ---------------- launch ------------------------------------------------------

extern "C" void kernel_launch(void* const* d_in, const int* in_sizes, int n_in,
                              void* d_out, int out_size) {
    const float* x      = (const float*)d_in[0];
    const int*   eidx   = (const int*)d_in[1];
    const int*   efeat  = (const int*)d_in[2];
    const float* weight = (const float*)d_in[3];
    const float* emb0   = (const float*)d_in[4];
    const float* emb1   = (const float*)d_in[5];
    const float* emb2   = (const float*)d_in[6];
    float*       out    = (float*)d_out;

    int n = in_sizes[0] / C;       // 50000
    int e = in_sizes[1] / 2;       // 625000
    const int* row = eidx;
    const int* col = eidx + e;

    static cudaStream_t s2 = nullptr;
    static cudaEvent_t evFork = nullptr, evJoin = nullptr;
    if (!s2) {
        cudaStreamCreateWithFlags(&s2, cudaStreamNonBlocking);
        cudaEventCreateWithFlags(&evFork, cudaEventDisableTiming);
        cudaEventCreateWithFlags(&evJoin, cudaEventDisableTiming);
    }

    int gemm_smem = (64 + 128) * GP * (int)sizeof(unsigned);  // 101376
    cudaFuncSetAttribute(k_gemm, cudaFuncAttributeMaxDynamicSharedMemorySize, gemm_smem);

    int tpb = 512;
    int nbT = (n + 511) / 512;     // scan tiles (98 <= 128)

    // fork: gemm on s2 runs concurrently with the prep chain on stream 0
    cudaEventRecord(evFork, 0);
    cudaStreamWaitEvent(s2, evFork, 0);
    k_gemm <<<(n + 63) / 64, 256, gemm_smem, s2>>>(x, weight, n);

    k_count<<<(e + tpb - 1) / tpb, tpb>>>(row, col, emb0, emb1, emb2, e);
    k_scan1<<<nbT, 512>>>(n);
    k_sprep<<<(e + tpb - 1) / tpb, tpb>>>(row, col, efeat, n, nbT, e);

    // join, then aggregate
    cudaEventRecord(evJoin, s2);
    cudaStreamWaitEvent(0, evJoin, 0);
    k_agg  <<<(n * 32 + 255) / 256, 256>>>(out, n);
}